// round 13
// baseline (speedup 1.0000x reference)
#include <cuda_runtime.h>
#include <math.h>

#define Bsz 64
#define Tn  12
#define Dd  256
#define Vv  512
#define Ss  512
#define NB  128   // all CTAs co-resident in one wave (128 <= 148 SMs)

// ---- persistent scratch (no allocations allowed) ----
__device__ unsigned g_ep[NB * 16];                // per-block launch counters (64B stride)
__device__ unsigned g_gsF[Bsz * 16];              // gs ready flags   (64B stride)
__device__ unsigned g_mgF[Bsz * 16];              // map-gate flags   (64B stride)
__device__ unsigned g_hF[32 * 16];                // h tile flags [z*16+rowt]
__device__ float    g_gs[Bsz * 2 * Dd];           // graph_state [64][512]
__device__ float    g_mg[Bsz][Tn];                // map gates (producer->walker)
__device__ __align__(16) float g_h[2 * Bsz * Dd]; // gelu'd hidden [z][64][256]

__device__ __forceinline__ float gelu_exact(float x) {
    return 0.5f * x * (1.0f + erff(x * 0.70710678118654752440f));
}
__device__ __forceinline__ float sigmoidf_(float x) {
    return 1.0f / (1.0f + expf(-x));
}
__device__ __forceinline__ unsigned ldvol(const unsigned* p) {
    return *(volatile const unsigned*)p;
}
__device__ __forceinline__ void rel_add(unsigned* p) {
    asm volatile("red.release.gpu.global.add.u32 [%0], 1;" :: "l"(p) : "memory");
}
__device__ __forceinline__ unsigned acq_ld(const unsigned* p) {
    unsigned v;
    asm volatile("ld.acquire.gpu.global.u32 %0, [%1];" : "=r"(v) : "l"(p) : "memory");
    return v;
}

// ---------------------------------------------------------------------------
__global__ void __launch_bounds__(256)
k_all(const int* __restrict__ marker, const int* __restrict__ srcI,
      const int* __restrict__ sv,
      const int* __restrict__ tsymI, const int* __restrict__ tsv,
      const int* __restrict__ tvalI, const int* __restrict__ tvv,
      const int* __restrict__ qI, const int* __restrict__ qV,
      const float* __restrict__ evidence,
      const float* __restrict__ symbol_emb, const float* __restrict__ value_emb,
      const float* __restrict__ Wmg1, const float* __restrict__ bmg1,
      const float* __restrict__ Wmg2, const float* __restrict__ bmg2,
      const float* __restrict__ Wsg1, const float* __restrict__ bsg1,
      const float* __restrict__ Wsg2, const float* __restrict__ bsg2,
      const float* __restrict__ Wf1,  const float* __restrict__ bf1,
      const float* __restrict__ Wf2,  const float* __restrict__ bf2,
      const float* __restrict__ Wo1,  const float* __restrict__ bo1,
      const float* __restrict__ Wo2,  const float* __restrict__ bo2,
      float* __restrict__ out)
{
    const int bx  = blockIdx.x;
    const int tid = threadIdx.x;
    const int lane = tid & 31, w = tid >> 5;

    __shared__ __align__(16) float pool[7168];     // 28KB, reused per phase
    __shared__ int   e_m[Tn], e_src[Tn], e_sv[Tn], e_ts[Tn], e_tsv[Tn], e_tv[Tn], e_tvv[Tn];
    __shared__ int   jobT[2][Tn];
    __shared__ int   nJob[2];
    __shared__ float gateL[Tn];                    // locally computed gates
    __shared__ float red[4][8];
    __shared__ int   wsI[40]; __shared__ float wsW[40];   // 1+3*12 = 37 used
    __shared__ int   avI[Tn]; __shared__ float avW[Tn];
    __shared__ unsigned s_L;
    __shared__ int   s_q; __shared__ float s_qv;

    // per-block private launch counter: zero contention, graph-replay safe
    if (tid == 0) {
        unsigned v = ldvol(&g_ep[bx * 16]);
        *(volatile unsigned*)&g_ep[bx * 16] = v + 1u;
        s_L = v;
    }

    // ======================= PHASE 1 =========================================
    // g=0: step gates (local) + walk + gather.  g=1: map gates -> global.
    const int b = bx & (Bsz - 1);
    const int g = bx >> 6;
    const int gt = 1 - g;                  // gate type computed here: 0=map, 1=step

    // --- gate-W1 slice prefetch: addresses depend only on bx/tid -------------
    const int cgW = w & 1, kqW = w >> 1;
    const int colb = cgW * 128 + lane * 4;
    const float* W1g = gt ? Wsg1 : Wmg1;
    const float* Wp1 = W1g + (kqW * 64) * Dd + colb;
    float4 pw[16];
    #pragma unroll
    for (int i = 0; i < 16; i++) pw[i] = *(const float4*)(Wp1 + i * Dd);

    // --- all 12 evidence rows staged unconditionally (indep of ballot) -------
    float* s_ev   = pool;                  // [12][256]
    float* s_part = pool + Tn * Dd;        // [4][4][256]
    #pragma unroll
    for (int r = 0; r < Tn; r++)
        s_ev[r * Dd + tid] = evidence[(b * Tn + r) * Dd + tid];

    // parallel event load: 84 threads, one LDG each
    if (tid < 84) {
        const int a = tid / 12, t = tid - a * 12;
        const int idx = b * Tn + t;
        int v;
        switch (a) {
            case 0: e_m[t]   = marker[idx]; break;
            case 1: v = srcI[idx];  e_src[t] = min(max(v, 0), Ss - 1); break;
            case 2: e_sv[t]  = sv[idx]; break;
            case 3: v = tsymI[idx]; e_ts[t]  = min(max(v, 0), Ss - 1); break;
            case 4: e_tsv[t] = tsv[idx]; break;
            case 5: v = tvalI[idx]; e_tv[t]  = min(max(v, 0), Vv - 1); break;
            case 6: e_tvv[t] = tvv[idx]; break;
        }
    } else if (tid == 84) {
        s_q = min(max(qI[b], 0), Ss - 1); s_qv = (float)qV[b];
    }
    __syncthreads();

    if (w == 0) {
        int fm = 0, fs = 0;
        if (lane < Tn) {
            int m = e_m[lane];
            fm = (((m == 0) || (m == 1)) && e_sv[lane] > 0 && e_tvv[lane] > 0) ? 1 : 0;
            fs = ((m == 2) && e_sv[lane] > 0 && e_tsv[lane] > 0) ? 1 : 0;
        }
        unsigned bm = __ballot_sync(0xffffffffu, fm);
        unsigned bs = __ballot_sync(0xffffffffu, fs);
        if (fm) jobT[0][__popc(bm & ((1u << lane) - 1u))] = lane;
        if (fs) jobT[1][__popc(bs & ((1u << lane) - 1u))] = lane;
        if (lane == 0) { nJob[0] = __popc(bm); nJob[1] = __popc(bs); }
    }
    __syncthreads();

    const unsigned Lt = s_L + 1u;
    const int nj = nJob[gt];

    // gate MLP: epilogue helper (bias+gelu+*W2, cross-warp reduce, sigmoid)
    {
        const float* B1 = gt ? bsg1 : bmg1;
        const float* W2 = gt ? Wsg2 : Wmg2;
        const float  b2 = gt ? bsg2[0] : bmg2[0];

        auto epilogue = [&](int j0, int cnt) {
            float b1v = B1[tid], w2v = W2[tid];
            for (int q = 0; q < cnt; q++) {
                float h = gelu_exact(s_part[(0 * 4 + q) * Dd + tid] + s_part[(1 * 4 + q) * Dd + tid]
                                   + s_part[(2 * 4 + q) * Dd + tid] + s_part[(3 * 4 + q) * Dd + tid]
                                   + b1v) * w2v;
                #pragma unroll
                for (int off = 16; off > 0; off >>= 1)
                    h += __shfl_down_sync(0xffffffffu, h, off);
                if (lane == 0) red[q][w] = h;
            }
            __syncthreads();
            if (tid < cnt) {
                float s = red[tid][0] + red[tid][1] + red[tid][2] + red[tid][3]
                        + red[tid][4] + red[tid][5] + red[tid][6] + red[tid][7];
                float gate = sigmoidf_(s + b2);
                if (g == 0) gateL[j0 + tid] = gate;      // step gates stay local
                else        g_mg[b][j0 + tid] = gate;    // map gates -> global
            }
            __syncthreads();
        };

        if (nj > 0) {   // peeled pass 0 with register-prefetched first half
            int cnt = nj; if (cnt > 4) cnt = 4;
            const float* x0 = s_ev + jobT[gt][0] * Dd;
            const float* x1 = s_ev + jobT[gt][cnt > 1 ? 1 : 0] * Dd;
            const float* x2 = s_ev + jobT[gt][cnt > 2 ? 2 : 0] * Dd;
            const float* x3 = s_ev + jobT[gt][cnt > 3 ? 3 : 0] * Dd;

            float4 a0 = {0,0,0,0}, a1 = {0,0,0,0}, a2 = {0,0,0,0}, a3 = {0,0,0,0};
            #pragma unroll
            for (int kk = 0; kk < 16; kk++) {
                float4 wv = pw[kk];
                int k = kqW * 64 + kk;
                float v0 = x0[k], v1 = x1[k], v2 = x2[k], v3 = x3[k];
                a0.x += v0*wv.x; a0.y += v0*wv.y; a0.z += v0*wv.z; a0.w += v0*wv.w;
                a1.x += v1*wv.x; a1.y += v1*wv.y; a1.z += v1*wv.z; a1.w += v1*wv.w;
                a2.x += v2*wv.x; a2.y += v2*wv.y; a2.z += v2*wv.z; a2.w += v2*wv.w;
                a3.x += v3*wv.x; a3.y += v3*wv.y; a3.z += v3*wv.z; a3.w += v3*wv.w;
            }
            #pragma unroll 16
            for (int kk = 16; kk < 64; kk++) {
                float4 wv = *(const float4*)(Wp1 + kk * Dd);
                int k = kqW * 64 + kk;
                float v0 = x0[k], v1 = x1[k], v2 = x2[k], v3 = x3[k];
                a0.x += v0*wv.x; a0.y += v0*wv.y; a0.z += v0*wv.z; a0.w += v0*wv.w;
                a1.x += v1*wv.x; a1.y += v1*wv.y; a1.z += v1*wv.z; a1.w += v1*wv.w;
                a2.x += v2*wv.x; a2.y += v2*wv.y; a2.z += v2*wv.z; a2.w += v2*wv.w;
                a3.x += v3*wv.x; a3.y += v3*wv.y; a3.z += v3*wv.z; a3.w += v3*wv.w;
            }
            *(float4*)&s_part[(kqW * 4 + 0) * Dd + colb] = a0;
            *(float4*)&s_part[(kqW * 4 + 1) * Dd + colb] = a1;
            *(float4*)&s_part[(kqW * 4 + 2) * Dd + colb] = a2;
            *(float4*)&s_part[(kqW * 4 + 3) * Dd + colb] = a3;
            __syncthreads();
            epilogue(0, cnt);
        }

        for (int j0 = 4; j0 < nj; j0 += 4) {     // rare overflow passes
            int cnt = nj - j0; if (cnt > 4) cnt = 4;
            const float* x0 = s_ev + jobT[gt][j0] * Dd;
            const float* x1 = s_ev + jobT[gt][j0 + (cnt > 1 ? 1 : 0)] * Dd;
            const float* x2 = s_ev + jobT[gt][j0 + (cnt > 2 ? 2 : 0)] * Dd;
            const float* x3 = s_ev + jobT[gt][j0 + (cnt > 3 ? 3 : 0)] * Dd;

            float4 a0 = {0,0,0,0}, a1 = {0,0,0,0}, a2 = {0,0,0,0}, a3 = {0,0,0,0};
            #pragma unroll 16
            for (int kk = 0; kk < 64; kk++) {
                float4 wv = *(const float4*)(Wp1 + kk * Dd);
                int k = kqW * 64 + kk;
                float v0 = x0[k], v1 = x1[k], v2 = x2[k], v3 = x3[k];
                a0.x += v0*wv.x; a0.y += v0*wv.y; a0.z += v0*wv.z; a0.w += v0*wv.w;
                a1.x += v1*wv.x; a1.y += v1*wv.y; a1.z += v1*wv.z; a1.w += v1*wv.w;
                a2.x += v2*wv.x; a2.y += v2*wv.y; a2.z += v2*wv.z; a2.w += v2*wv.w;
                a3.x += v3*wv.x; a3.y += v3*wv.y; a3.z += v3*wv.z; a3.w += v3*wv.w;
            }
            *(float4*)&s_part[(kqW * 4 + 0) * Dd + colb] = a0;
            *(float4*)&s_part[(kqW * 4 + 1) * Dd + colb] = a1;
            *(float4*)&s_part[(kqW * 4 + 2) * Dd + colb] = a2;
            *(float4*)&s_part[(kqW * 4 + 3) * Dd + colb] = a3;
            __syncthreads();
            epilogue(j0, cnt);
        }
    }

    if (g == 1) {
        if (tid == 0) rel_add(&g_mgF[b * 16]);
    } else {
        const int nm = nJob[0], ns = nJob[1];

        // warp-collective sparse walk using LOCAL step gates (no wait!)
        if (w == 0) {
            #pragma unroll
            for (int i = lane; i < 40; i += 32) { wsI[i] = 0; wsW[i] = 0.f; }
            if (lane < Tn) { avI[lane] = 0; avW[lane] = 0.f; }

            int srcE = 0, tgtE = 0; float wE = 0.f;
            if (lane < ns) {
                int t = jobT[1][lane];
                srcE = e_src[t]; tgtE = e_ts[t]; wE = gateL[lane];
            }
            const int q = s_q; const float qv = s_qv;

            float c1 = (lane < ns && srcE == q) ? wE * qv : 0.f;
            float c2 = 0.f;
            for (int e = 0; e < ns; e++) {
                float ce = __shfl_sync(0xffffffffu, c1, e);
                int   te = __shfl_sync(0xffffffffu, tgtE, e);
                if (te == srcE) c2 += ce;
            }
            c2 *= wE;
            float c3 = 0.f;
            for (int e = 0; e < ns; e++) {
                float ce = __shfl_sync(0xffffffffu, c2, e);
                int   te = __shfl_sync(0xffffffffu, tgtE, e);
                if (te == srcE) c3 += ce;
            }
            c3 *= wE;
            float c123 = c1 + c2 + c3;

            int mSrc = 0, mTgt = 0;
            if (lane < nm) {
                int t = jobT[0][lane];
                mSrc = e_src[t]; mTgt = e_tv[t];
            }
            float acc = (mSrc == q) ? qv : 0.f;
            for (int e = 0; e < ns; e++) {
                float ce = __shfl_sync(0xffffffffu, c123, e);
                int   te = __shfl_sync(0xffffffffu, tgtE, e);
                if (te == mSrc) acc += ce;
            }

            __syncwarp();
            if (lane == 0) { wsI[0] = q; wsW[0] = qv; }
            if (lane < ns) {
                wsI[1 + lane]          = tgtE; wsW[1 + lane]          = c1;
                wsI[1 + ns + lane]     = tgtE; wsW[1 + ns + lane]     = c2;
                wsI[1 + 2 * ns + lane] = tgtE; wsW[1 + 2 * ns + lane] = c3;
            }
            if (lane < nm) { avI[lane] = mTgt; avW[lane] = acc; }   // gate applied later
        }
        __syncthreads();

        // symbol gather overlaps the map-gate hop
        float ss = 0.f;
        #pragma unroll
        for (int p = 0; p < 37; p++)
            ss += wsW[p] * __ldg(&symbol_emb[wsI[p] * Dd + tid]);

        if (tid == 0)
            while ((int)(acq_ld(&g_mgF[b * 16]) - Lt) < 0) { }
        __syncthreads();
        if (w == 0 && lane < nm) avW[lane] *= __ldcg(&g_mg[b][lane]);
        __syncthreads();

        float vv = 0.f;
        #pragma unroll
        for (int p = 0; p < Tn; p++)
            vv += avW[p] * __ldg(&value_emb[avI[p] * Dd + tid]);
        g_gs[b * (2 * Dd) + tid]      = ss;
        g_gs[b * (2 * Dd) + Dd + tid] = vv;
        __syncthreads();
        if (tid == 0) rel_add(&g_gsF[b * 16]);
    }

    // ======================= PHASE 2: hidden (full K=512) ====================
    // tile = bx: colt(4 x 64 cols) x rowt(16 x 4 rows) x z(2)
    {
        const int colt = bx & 3, rowt = (bx >> 2) & 15, z = bx >> 6;
        const float* W1 = z ? Wf1 : Wo1;
        const float* B1 = z ? bf1 : bo1;
        const int cg = tid & 15, kq = tid >> 4;       // 16 col-groups x 16 k-chunks
        const int colg = colt * 64 + cg * 4;
        const float* Wp = W1 + (kq * 32) * Dd + colg;

        // prefetch first half of W slice BEFORE the flag wait (indep of gs)
        float4 w0[16];
        #pragma unroll
        for (int i = 0; i < 16; i++) w0[i] = *(const float4*)(Wp + i * Dd);

        if (tid == 0) {
            const int b0 = rowt * 4;
            for (;;) {
                unsigned f0 = acq_ld(&g_gsF[(b0 + 0) * 16]);
                unsigned f1 = acq_ld(&g_gsF[(b0 + 1) * 16]);
                unsigned f2 = acq_ld(&g_gsF[(b0 + 2) * 16]);
                unsigned f3 = acq_ld(&g_gsF[(b0 + 3) * 16]);
                if ((int)(f0 - Lt) >= 0 && (int)(f1 - Lt) >= 0 &&
                    (int)(f2 - Lt) >= 0 && (int)(f3 - Lt) >= 0) break;
            }
        }
        __syncthreads();

        float* gs_s  = pool;           // [4][512]
        float* s_red = pool + 2048;    // [16][4][64]
        {
            const float4* src = (const float4*)&g_gs[rowt * 4 * 512];
            float4* dst = (float4*)gs_s;
            dst[tid]       = __ldcg(src + tid);
            dst[tid + 256] = __ldcg(src + tid + 256);
        }
        __syncthreads();

        // second half of W slice: issues while first-half FFMAs run
        float4 w1[16];
        #pragma unroll
        for (int i = 0; i < 16; i++) w1[i] = *(const float4*)(Wp + (16 + i) * Dd);

        float4 a0 = {0,0,0,0}, a1 = {0,0,0,0}, a2 = {0,0,0,0}, a3 = {0,0,0,0};
        #pragma unroll
        for (int kk = 0; kk < 16; kk++) {
            float4 wv = w0[kk];
            int k = kq * 32 + kk;
            float v0 = gs_s[k], v1 = gs_s[512 + k], v2 = gs_s[1024 + k], v3 = gs_s[1536 + k];
            a0.x += v0*wv.x; a0.y += v0*wv.y; a0.z += v0*wv.z; a0.w += v0*wv.w;
            a1.x += v1*wv.x; a1.y += v1*wv.y; a1.z += v1*wv.z; a1.w += v1*wv.w;
            a2.x += v2*wv.x; a2.y += v2*wv.y; a2.z += v2*wv.z; a2.w += v2*wv.w;
            a3.x += v3*wv.x; a3.y += v3*wv.y; a3.z += v3*wv.z; a3.w += v3*wv.w;
        }
        #pragma unroll
        for (int kk = 0; kk < 16; kk++) {
            float4 wv = w1[kk];
            int k = kq * 32 + 16 + kk;
            float v0 = gs_s[k], v1 = gs_s[512 + k], v2 = gs_s[1024 + k], v3 = gs_s[1536 + k];
            a0.x += v0*wv.x; a0.y += v0*wv.y; a0.z += v0*wv.z; a0.w += v0*wv.w;
            a1.x += v1*wv.x; a1.y += v1*wv.y; a1.z += v1*wv.z; a1.w += v1*wv.w;
            a2.x += v2*wv.x; a2.y += v2*wv.y; a2.z += v2*wv.z; a2.w += v2*wv.w;
            a3.x += v3*wv.x; a3.y += v3*wv.y; a3.z += v3*wv.z; a3.w += v3*wv.w;
        }
        *(float4*)&s_red[(kq * 4 + 0) * 64 + cg * 4] = a0;
        *(float4*)&s_red[(kq * 4 + 1) * 64 + cg * 4] = a1;
        *(float4*)&s_red[(kq * 4 + 2) * 64 + cg * 4] = a2;
        *(float4*)&s_red[(kq * 4 + 3) * 64 + cg * 4] = a3;
        __syncthreads();

        {
            int r = tid >> 6, c = tid & 63;
            float s = 0.f;
            #pragma unroll
            for (int k2 = 0; k2 < 16; k2++) s += s_red[(k2 * 4 + r) * 64 + c];
            float hv = gelu_exact(s + B1[colt * 64 + c]);
            g_h[(z * Bsz + rowt * 4 + r) * Dd + colt * 64 + c] = hv;
        }
        __syncthreads();
        if (tid == 0) rel_add(&g_hF[(z * 16 + rowt) * 16]);
    }

    // ======================= PHASE 3: output (full K=256, direct store) ======
    if (bx < 96) {
        int z, rowt, colt;
        if (bx < 64) { z = 0; rowt = bx >> 2;        colt = bx & 3; }
        else         { z = 1; rowt = (bx - 64) >> 1; colt = (bx - 64) & 1; }
        const int OW = z ? Dd : Vv;
        const float* W2 = z ? Wf2 : Wo2;
        const float* B2 = z ? bf2 : bo2;
        const int cg = tid & 31, kq = tid >> 5;      // 32 col-groups x 8 k-chunks
        const int colg = colt * 128 + cg * 4;
        const float* Wp = W2 + (kq * 32) * OW + colg;

        // prefetch first half of W2 slice before the h wait
        float4 w0[16];
        #pragma unroll
        for (int i = 0; i < 16; i++) w0[i] = *(const float4*)(Wp + i * OW);

        if (tid == 0) {
            const unsigned tgt = 4u * Lt;
            while ((int)(acq_ld(&g_hF[(z * 16 + rowt) * 16]) - tgt) < 0) { }
        }
        __syncthreads();

        float* h_s   = pool;          // [4][256]
        float* s_red = pool + 1024;   // [8][4][128]
        ((float4*)h_s)[tid] = __ldcg((const float4*)&g_h[(z * Bsz + rowt * 4) * Dd] + tid);
        __syncthreads();

        float4 w1[16];
        #pragma unroll
        for (int i = 0; i < 16; i++) w1[i] = *(const float4*)(Wp + (16 + i) * OW);

        float4 a0 = {0,0,0,0}, a1 = {0,0,0,0}, a2 = {0,0,0,0}, a3 = {0,0,0,0};
        #pragma unroll
        for (int kk = 0; kk < 16; kk++) {
            float4 wv = w0[kk];
            int k = kq * 32 + kk;
            float v0 = h_s[k], v1 = h_s[256 + k], v2 = h_s[512 + k], v3 = h_s[768 + k];
            a0.x += v0*wv.x; a0.y += v0*wv.y; a0.z += v0*wv.z; a0.w += v0*wv.w;
            a1.x += v1*wv.x; a1.y += v1*wv.y; a1.z += v1*wv.z; a1.w += v1*wv.w;
            a2.x += v2*wv.x; a2.y += v2*wv.y; a2.z += v2*wv.z; a2.w += v2*wv.w;
            a3.x += v3*wv.x; a3.y += v3*wv.y; a3.z += v3*wv.z; a3.w += v3*wv.w;
        }
        #pragma unroll
        for (int kk = 0; kk < 16; kk++) {
            float4 wv = w1[kk];
            int k = kq * 32 + 16 + kk;
            float v0 = h_s[k], v1 = h_s[256 + k], v2 = h_s[512 + k], v3 = h_s[768 + k];
            a0.x += v0*wv.x; a0.y += v0*wv.y; a0.z += v0*wv.z; a0.w += v0*wv.w;
            a1.x += v1*wv.x; a1.y += v1*wv.y; a1.z += v1*wv.z; a1.w += v1*wv.w;
            a2.x += v2*wv.x; a2.y += v2*wv.y; a2.z += v2*wv.z; a2.w += v2*wv.w;
            a3.x += v3*wv.x; a3.y += v3*wv.y; a3.z += v3*wv.z; a3.w += v3*wv.w;
        }
        *(float4*)&s_red[(kq * 4 + 0) * 128 + cg * 4] = a0;
        *(float4*)&s_red[(kq * 4 + 1) * 128 + cg * 4] = a1;
        *(float4*)&s_red[(kq * 4 + 2) * 128 + cg * 4] = a2;
        *(float4*)&s_red[(kq * 4 + 3) * 128 + cg * 4] = a3;
        __syncthreads();

        float* ob = z ? (out + Bsz * Vv) : out;
        #pragma unroll
        for (int u = 0; u < 2; u++) {
            int idx = tid + u * 256;
            int r = idx >> 7, c = idx & 127;
            float s = 0.f;
            #pragma unroll
            for (int k2 = 0; k2 < 8; k2++) s += s_red[(k2 * 4 + r) * 128 + c];
            ob[(rowt * 4 + r) * OW + colt * 128 + c] = s + B2[colt * 128 + c];
        }
    }
}

// ---------------------------------------------------------------------------
extern "C" void kernel_launch(void* const* d_in, const int* in_sizes, int n_in,
                              void* d_out, int out_size)
{
    const int*   marker     = (const int*)d_in[0];
    const int*   srcI       = (const int*)d_in[1];
    const int*   sv         = (const int*)d_in[2];
    const int*   tsymI      = (const int*)d_in[3];
    const int*   tsv        = (const int*)d_in[4];
    const int*   tvalI      = (const int*)d_in[5];
    const int*   tvv        = (const int*)d_in[6];
    const int*   qI         = (const int*)d_in[7];
    const int*   qV         = (const int*)d_in[8];
    const float* evidence   = (const float*)d_in[9];
    const float* symbol_emb = (const float*)d_in[10];
    const float* value_emb  = (const float*)d_in[11];
    const float* Wmg1 = (const float*)d_in[12]; const float* bmg1 = (const float*)d_in[13];
    const float* Wmg2 = (const float*)d_in[14]; const float* bmg2 = (const float*)d_in[15];
    const float* Wsg1 = (const float*)d_in[16]; const float* bsg1 = (const float*)d_in[17];
    const float* Wsg2 = (const float*)d_in[18]; const float* bsg2 = (const float*)d_in[19];
    const float* Wf1  = (const float*)d_in[20]; const float* bf1  = (const float*)d_in[21];
    const float* Wf2  = (const float*)d_in[22]; const float* bf2  = (const float*)d_in[23];
    const float* Wo1  = (const float*)d_in[24]; const float* bo1  = (const float*)d_in[25];
    const float* Wo2  = (const float*)d_in[26]; const float* bo2  = (const float*)d_in[27];
    float* out = (float*)d_out;

    k_all<<<NB, 256>>>(marker, srcI, sv, tsymI, tsv, tvalI, tvv, qI, qV,
                       evidence, symbol_emb, value_emb,
                       Wmg1, bmg1, Wmg2, bmg2, Wsg1, bsg1, Wsg2, bsg2,
                       Wf1, bf1, Wf2, bf2, Wo1, bo1, Wo2, bo2, out);
}

// round 15
// speedup vs baseline: 1.4037x; 1.4037x over previous
#include <cuda_runtime.h>
#include <math.h>

#define Bsz 64
#define Tn  12
#define Dd  256
#define Vv  512
#define Ss  512
#define NB  128   // all CTAs co-resident in one wave (128 <= 148 SMs)

// ---- persistent scratch (no allocations allowed) ----
__device__ unsigned g_ep[NB * 16];                // per-block launch counters (64B stride)
__device__ unsigned g_gsF[Bsz * 16];              // gs ready flags   (64B stride)
__device__ unsigned g_mgF[Bsz * 16];              // map-gate flags   (64B stride)
__device__ unsigned g_hF[32 * 16];                // h tile flags [z*16+rowt]
__device__ float    g_gs[Bsz * 2 * Dd];           // graph_state [64][512]
__device__ float    g_mg[Bsz][Tn];                // map gates (producer->walker)
__device__ __align__(16) float g_h[2 * Bsz * Dd]; // gelu'd hidden [z][64][256]

__device__ __forceinline__ float gelu_exact(float x) {
    return 0.5f * x * (1.0f + erff(x * 0.70710678118654752440f));
}
__device__ __forceinline__ float sigmoidf_(float x) {
    return 1.0f / (1.0f + expf(-x));
}
__device__ __forceinline__ unsigned ldvol(const unsigned* p) {
    return *(volatile const unsigned*)p;
}
__device__ __forceinline__ void rel_add(unsigned* p) {
    asm volatile("red.release.gpu.global.add.u32 [%0], 1;" :: "l"(p) : "memory");
}
__device__ __forceinline__ unsigned acq_ld(const unsigned* p) {
    unsigned v;
    asm volatile("ld.acquire.gpu.global.u32 %0, [%1];" : "=r"(v) : "l"(p) : "memory");
    return v;
}
__device__ __forceinline__ void l2_prefetch(const void* p) {
    asm volatile("prefetch.global.L2 [%0];" :: "l"(p));
}

// ---------------------------------------------------------------------------
__global__ void __launch_bounds__(256)
k_all(const int* __restrict__ marker, const int* __restrict__ srcI,
      const int* __restrict__ sv,
      const int* __restrict__ tsymI, const int* __restrict__ tsv,
      const int* __restrict__ tvalI, const int* __restrict__ tvv,
      const int* __restrict__ qI, const int* __restrict__ qV,
      const float* __restrict__ evidence,
      const float* __restrict__ symbol_emb, const float* __restrict__ value_emb,
      const float* __restrict__ Wmg1, const float* __restrict__ bmg1,
      const float* __restrict__ Wmg2, const float* __restrict__ bmg2,
      const float* __restrict__ Wsg1, const float* __restrict__ bsg1,
      const float* __restrict__ Wsg2, const float* __restrict__ bsg2,
      const float* __restrict__ Wf1,  const float* __restrict__ bf1,
      const float* __restrict__ Wf2,  const float* __restrict__ bf2,
      const float* __restrict__ Wo1,  const float* __restrict__ bo1,
      const float* __restrict__ Wo2,  const float* __restrict__ bo2,
      float* __restrict__ out)
{
    const int bx  = blockIdx.x;
    const int tid = threadIdx.x;
    const int lane = tid & 31, w = tid >> 5;

    __shared__ __align__(16) float pool[7168];     // 28KB, reused per phase
    __shared__ int   e_m[Tn], e_src[Tn], e_sv[Tn], e_ts[Tn], e_tsv[Tn], e_tv[Tn], e_tvv[Tn];
    __shared__ int   jobT[2][Tn];
    __shared__ int   nJob[2];
    __shared__ float gateL[Tn];                    // locally computed gates
    __shared__ float red[4][8];
    __shared__ int   wsI[40]; __shared__ float wsW[40];   // 1+3*12 = 37 used
    __shared__ int   avI[Tn]; __shared__ float avW[Tn];
    __shared__ unsigned s_L;
    __shared__ int   s_q; __shared__ float s_qv;

    // per-block private launch counter: zero contention, graph-replay safe
    if (tid == 0) {
        unsigned v = ldvol(&g_ep[bx * 16]);
        *(volatile unsigned*)&g_ep[bx * 16] = v + 1u;
        s_L = v;
    }

    // ======================= PHASE 1 =========================================
    // g=0: step gates (local) + walk + gather.  g=1: map gates -> global.
    const int b = bx & (Bsz - 1);
    const int g = bx >> 6;
    const int gt = 1 - g;                  // gate type computed here: 0=map, 1=step

    // register-free L2 warm-up of this block's gate-W1 slice (no retention)
    {
        const int cgP = w & 1, kqP = w >> 1;
        const float* W1g = gt ? Wsg1 : Wmg1;
        const float* Wpp = W1g + (kqP * 64) * Dd + cgP * 128 + lane * 4;
        #pragma unroll
        for (int i = 0; i < 64; i += 4)
            l2_prefetch(Wpp + i * Dd);
    }

    // parallel event load: 84 threads, one LDG each
    if (tid < 84) {
        const int a = tid / 12, t = tid - a * 12;
        const int idx = b * Tn + t;
        int v;
        switch (a) {
            case 0: e_m[t]   = marker[idx]; break;
            case 1: v = srcI[idx];  e_src[t] = min(max(v, 0), Ss - 1); break;
            case 2: e_sv[t]  = sv[idx]; break;
            case 3: v = tsymI[idx]; e_ts[t]  = min(max(v, 0), Ss - 1); break;
            case 4: e_tsv[t] = tsv[idx]; break;
            case 5: v = tvalI[idx]; e_tv[t]  = min(max(v, 0), Vv - 1); break;
            case 6: e_tvv[t] = tvv[idx]; break;
        }
    } else if (tid == 84) {
        s_q = min(max(qI[b], 0), Ss - 1); s_qv = (float)qV[b];
    }
    __syncthreads();

    if (w == 0) {
        int fm = 0, fs = 0;
        if (lane < Tn) {
            int m = e_m[lane];
            fm = (((m == 0) || (m == 1)) && e_sv[lane] > 0 && e_tvv[lane] > 0) ? 1 : 0;
            fs = ((m == 2) && e_sv[lane] > 0 && e_tsv[lane] > 0) ? 1 : 0;
        }
        unsigned bm = __ballot_sync(0xffffffffu, fm);
        unsigned bs = __ballot_sync(0xffffffffu, fs);
        if (fm) jobT[0][__popc(bm & ((1u << lane) - 1u))] = lane;
        if (fs) jobT[1][__popc(bs & ((1u << lane) - 1u))] = lane;
        if (lane == 0) { nJob[0] = __popc(bm); nJob[1] = __popc(bs); }
    }
    __syncthreads();

    const unsigned Lt = s_L + 1u;
    const int nj = nJob[gt];

    // stage active jobs' evidence rows
    float* s_ev   = pool;                  // [<=12][256]
    float* s_part = pool + Tn * Dd;        // [4][4][256]
    for (int jj = 0; jj < nj; jj++)
        s_ev[jj * Dd + tid] = evidence[(b * Tn + jobT[gt][jj]) * Dd + tid];
    __syncthreads();

    // gate MLP passes for this block's gate type
    {
        const float* W1 = gt ? Wsg1 : Wmg1;
        const float* B1 = gt ? bsg1 : bmg1;
        const float* W2 = gt ? Wsg2 : Wmg2;
        const float  b2 = gt ? bsg2[0] : bmg2[0];
        const int cg = w & 1, kq = w >> 1;
        const int colb = cg * 128 + lane * 4;

        for (int j0 = 0; j0 < nj; j0 += 4) {
            int cnt = nj - j0; if (cnt > 4) cnt = 4;
            const float* Wp = W1 + (kq * 64) * Dd + colb;
            const float* x0 = s_ev + (j0) * Dd;
            const float* x1 = s_ev + (j0 + (cnt > 1 ? 1 : 0)) * Dd;

            if (cnt <= 2) {
                float4 a0 = {0,0,0,0}, a1 = {0,0,0,0};
                #pragma unroll 16
                for (int kk = 0; kk < 64; kk++) {
                    float4 wv = *(const float4*)(Wp + kk * Dd);
                    int k = kq * 64 + kk;
                    float v0 = x0[k], v1 = x1[k];
                    a0.x += v0*wv.x; a0.y += v0*wv.y; a0.z += v0*wv.z; a0.w += v0*wv.w;
                    a1.x += v1*wv.x; a1.y += v1*wv.y; a1.z += v1*wv.z; a1.w += v1*wv.w;
                }
                *(float4*)&s_part[(kq * 4 + 0) * Dd + colb] = a0;
                *(float4*)&s_part[(kq * 4 + 1) * Dd + colb] = a1;
            } else {
                const float* x2 = s_ev + (j0 + 2) * Dd;
                const float* x3 = s_ev + (j0 + (cnt > 3 ? 3 : 2)) * Dd;
                float4 a0 = {0,0,0,0}, a1 = {0,0,0,0}, a2 = {0,0,0,0}, a3 = {0,0,0,0};
                #pragma unroll 16
                for (int kk = 0; kk < 64; kk++) {
                    float4 wv = *(const float4*)(Wp + kk * Dd);
                    int k = kq * 64 + kk;
                    float v0 = x0[k], v1 = x1[k], v2 = x2[k], v3 = x3[k];
                    a0.x += v0*wv.x; a0.y += v0*wv.y; a0.z += v0*wv.z; a0.w += v0*wv.w;
                    a1.x += v1*wv.x; a1.y += v1*wv.y; a1.z += v1*wv.z; a1.w += v1*wv.w;
                    a2.x += v2*wv.x; a2.y += v2*wv.y; a2.z += v2*wv.z; a2.w += v2*wv.w;
                    a3.x += v3*wv.x; a3.y += v3*wv.y; a3.z += v3*wv.z; a3.w += v3*wv.w;
                }
                *(float4*)&s_part[(kq * 4 + 0) * Dd + colb] = a0;
                *(float4*)&s_part[(kq * 4 + 1) * Dd + colb] = a1;
                *(float4*)&s_part[(kq * 4 + 2) * Dd + colb] = a2;
                *(float4*)&s_part[(kq * 4 + 3) * Dd + colb] = a3;
            }
            __syncthreads();

            float b1v = B1[tid], w2v = W2[tid];
            for (int q = 0; q < cnt; q++) {
                float h = gelu_exact(s_part[(0 * 4 + q) * Dd + tid] + s_part[(1 * 4 + q) * Dd + tid]
                                   + s_part[(2 * 4 + q) * Dd + tid] + s_part[(3 * 4 + q) * Dd + tid]
                                   + b1v) * w2v;
                #pragma unroll
                for (int off = 16; off > 0; off >>= 1)
                    h += __shfl_down_sync(0xffffffffu, h, off);
                if (lane == 0) red[q][w] = h;
            }
            __syncthreads();
            if (tid < cnt) {
                float s = red[tid][0] + red[tid][1] + red[tid][2] + red[tid][3]
                        + red[tid][4] + red[tid][5] + red[tid][6] + red[tid][7];
                float gate = sigmoidf_(s + b2);
                if (g == 0) gateL[j0 + tid] = gate;      // step gates stay local
                else        g_mg[b][j0 + tid] = gate;    // map gates -> global
            }
            __syncthreads();
        }
    }

    if (g == 1) {
        if (tid == 0) rel_add(&g_mgF[b * 16]);
    } else {
        const int nm = nJob[0], ns = nJob[1];

        // warp-collective sparse walk using LOCAL step gates (no wait!)
        if (w == 0) {
            #pragma unroll
            for (int i = lane; i < 40; i += 32) { wsI[i] = 0; wsW[i] = 0.f; }
            if (lane < Tn) { avI[lane] = 0; avW[lane] = 0.f; }

            int srcE = 0, tgtE = 0; float wE = 0.f;
            if (lane < ns) {
                int t = jobT[1][lane];
                srcE = e_src[t]; tgtE = e_ts[t]; wE = gateL[lane];
            }
            const int q = s_q; const float qv = s_qv;

            float c1 = (lane < ns && srcE == q) ? wE * qv : 0.f;
            float c2 = 0.f;
            for (int e = 0; e < ns; e++) {
                float ce = __shfl_sync(0xffffffffu, c1, e);
                int   te = __shfl_sync(0xffffffffu, tgtE, e);
                if (te == srcE) c2 += ce;
            }
            c2 *= wE;
            float c3 = 0.f;
            for (int e = 0; e < ns; e++) {
                float ce = __shfl_sync(0xffffffffu, c2, e);
                int   te = __shfl_sync(0xffffffffu, tgtE, e);
                if (te == srcE) c3 += ce;
            }
            c3 *= wE;
            float c123 = c1 + c2 + c3;

            int mSrc = 0, mTgt = 0;
            if (lane < nm) {
                int t = jobT[0][lane];
                mSrc = e_src[t]; mTgt = e_tv[t];
            }
            float acc = (mSrc == q) ? qv : 0.f;
            for (int e = 0; e < ns; e++) {
                float ce = __shfl_sync(0xffffffffu, c123, e);
                int   te = __shfl_sync(0xffffffffu, tgtE, e);
                if (te == mSrc) acc += ce;
            }

            __syncwarp();
            if (lane == 0) { wsI[0] = q; wsW[0] = qv; }
            if (lane < ns) {
                wsI[1 + lane]          = tgtE; wsW[1 + lane]          = c1;
                wsI[1 + ns + lane]     = tgtE; wsW[1 + ns + lane]     = c2;
                wsI[1 + 2 * ns + lane] = tgtE; wsW[1 + 2 * ns + lane] = c3;
            }
            if (lane < nm) { avI[lane] = mTgt; avW[lane] = acc; }   // gate applied later
        }
        __syncthreads();

        // symbol gather overlaps the map-gate hop
        float ss = 0.f;
        #pragma unroll
        for (int p = 0; p < 37; p++)
            ss += wsW[p] * __ldg(&symbol_emb[wsI[p] * Dd + tid]);

        if (tid == 0)
            while ((int)(acq_ld(&g_mgF[b * 16]) - Lt) < 0) { }
        __syncthreads();
        if (w == 0 && lane < nm) avW[lane] *= __ldcg(&g_mg[b][lane]);
        __syncthreads();

        float vv = 0.f;
        #pragma unroll
        for (int p = 0; p < Tn; p++)
            vv += avW[p] * __ldg(&value_emb[avI[p] * Dd + tid]);
        g_gs[b * (2 * Dd) + tid]      = ss;
        g_gs[b * (2 * Dd) + Dd + tid] = vv;
        __syncthreads();
        if (tid == 0) rel_add(&g_gsF[b * 16]);
    }

    // ======================= PHASE 2: hidden (full K=512) ====================
    // tile = bx: colt(4 x 64 cols) x rowt(16 x 4 rows) x z(2)
    {
        const int colt = bx & 3, rowt = (bx >> 2) & 15, z = bx >> 6;
        const float* W1 = z ? Wf1 : Wo1;
        const float* B1 = z ? bf1 : bo1;
        const int cg = tid & 15, kq = tid >> 4;       // 16 col-groups x 16 k-chunks
        const int colg = colt * 64 + cg * 4;
        const float* Wp = W1 + (kq * 32) * Dd + colg;

        // prefetch first half of W slice BEFORE the flag wait (indep of gs)
        float4 w0[16];
        #pragma unroll
        for (int i = 0; i < 16; i++) w0[i] = *(const float4*)(Wp + i * Dd);

        if (tid == 0) {
            const int b0 = rowt * 4;
            for (;;) {
                unsigned f0 = acq_ld(&g_gsF[(b0 + 0) * 16]);
                unsigned f1 = acq_ld(&g_gsF[(b0 + 1) * 16]);
                unsigned f2 = acq_ld(&g_gsF[(b0 + 2) * 16]);
                unsigned f3 = acq_ld(&g_gsF[(b0 + 3) * 16]);
                if ((int)(f0 - Lt) >= 0 && (int)(f1 - Lt) >= 0 &&
                    (int)(f2 - Lt) >= 0 && (int)(f3 - Lt) >= 0) break;
            }
        }
        __syncthreads();

        float* gs_s  = pool;           // [4][512]
        float* s_red = pool + 2048;    // [16][4][64]
        {
            const float4* src = (const float4*)&g_gs[rowt * 4 * 512];
            float4* dst = (float4*)gs_s;
            dst[tid]       = __ldcg(src + tid);
            dst[tid + 256] = __ldcg(src + tid + 256);
        }
        __syncthreads();

        // second half of W slice: issues while first-half FFMAs run
        float4 w1[16];
        #pragma unroll
        for (int i = 0; i < 16; i++) w1[i] = *(const float4*)(Wp + (16 + i) * Dd);

        float4 a0 = {0,0,0,0}, a1 = {0,0,0,0}, a2 = {0,0,0,0}, a3 = {0,0,0,0};
        #pragma unroll
        for (int kk = 0; kk < 16; kk++) {
            float4 wv = w0[kk];
            int k = kq * 32 + kk;
            float v0 = gs_s[k], v1 = gs_s[512 + k], v2 = gs_s[1024 + k], v3 = gs_s[1536 + k];
            a0.x += v0*wv.x; a0.y += v0*wv.y; a0.z += v0*wv.z; a0.w += v0*wv.w;
            a1.x += v1*wv.x; a1.y += v1*wv.y; a1.z += v1*wv.z; a1.w += v1*wv.w;
            a2.x += v2*wv.x; a2.y += v2*wv.y; a2.z += v2*wv.z; a2.w += v2*wv.w;
            a3.x += v3*wv.x; a3.y += v3*wv.y; a3.z += v3*wv.z; a3.w += v3*wv.w;
        }
        #pragma unroll
        for (int kk = 0; kk < 16; kk++) {
            float4 wv = w1[kk];
            int k = kq * 32 + 16 + kk;
            float v0 = gs_s[k], v1 = gs_s[512 + k], v2 = gs_s[1024 + k], v3 = gs_s[1536 + k];
            a0.x += v0*wv.x; a0.y += v0*wv.y; a0.z += v0*wv.z; a0.w += v0*wv.w;
            a1.x += v1*wv.x; a1.y += v1*wv.y; a1.z += v1*wv.z; a1.w += v1*wv.w;
            a2.x += v2*wv.x; a2.y += v2*wv.y; a2.z += v2*wv.z; a2.w += v2*wv.w;
            a3.x += v3*wv.x; a3.y += v3*wv.y; a3.z += v3*wv.z; a3.w += v3*wv.w;
        }
        *(float4*)&s_red[(kq * 4 + 0) * 64 + cg * 4] = a0;
        *(float4*)&s_red[(kq * 4 + 1) * 64 + cg * 4] = a1;
        *(float4*)&s_red[(kq * 4 + 2) * 64 + cg * 4] = a2;
        *(float4*)&s_red[(kq * 4 + 3) * 64 + cg * 4] = a3;
        __syncthreads();

        {
            int r = tid >> 6, c = tid & 63;
            float s = 0.f;
            #pragma unroll
            for (int k2 = 0; k2 < 16; k2++) s += s_red[(k2 * 4 + r) * 64 + c];
            float hv = gelu_exact(s + B1[colt * 64 + c]);
            g_h[(z * Bsz + rowt * 4 + r) * Dd + colt * 64 + c] = hv;
        }
        __syncthreads();
        if (tid == 0) rel_add(&g_hF[(z * 16 + rowt) * 16]);
    }

    // ======================= PHASE 3: output (full K=256, direct store) ======
    if (bx < 96) {
        int z, rowt, colt;
        if (bx < 64) { z = 0; rowt = bx >> 2;        colt = bx & 3; }
        else         { z = 1; rowt = (bx - 64) >> 1; colt = (bx - 64) & 1; }
        const int OW = z ? Dd : Vv;
        const float* W2 = z ? Wf2 : Wo2;
        const float* B2 = z ? bf2 : bo2;
        const int cg = tid & 31, kq = tid >> 5;      // 32 col-groups x 8 k-chunks
        const int colg = colt * 128 + cg * 4;
        const float* Wp = W2 + (kq * 32) * OW + colg;

        // prefetch first half of W2 slice before the h wait
        float4 w0[16];
        #pragma unroll
        for (int i = 0; i < 16; i++) w0[i] = *(const float4*)(Wp + i * OW);

        if (tid == 0) {
            const unsigned tgt = 4u * Lt;
            while ((int)(acq_ld(&g_hF[(z * 16 + rowt) * 16]) - tgt) < 0) { }
        }
        __syncthreads();

        float* h_s   = pool;          // [4][256]
        float* s_red = pool + 1024;   // [8][4][128]
        ((float4*)h_s)[tid] = __ldcg((const float4*)&g_h[(z * Bsz + rowt * 4) * Dd] + tid);
        __syncthreads();

        float4 w1[16];
        #pragma unroll
        for (int i = 0; i < 16; i++) w1[i] = *(const float4*)(Wp + (16 + i) * OW);

        float4 a0 = {0,0,0,0}, a1 = {0,0,0,0}, a2 = {0,0,0,0}, a3 = {0,0,0,0};
        #pragma unroll
        for (int kk = 0; kk < 16; kk++) {
            float4 wv = w0[kk];
            int k = kq * 32 + kk;
            float v0 = h_s[k], v1 = h_s[256 + k], v2 = h_s[512 + k], v3 = h_s[768 + k];
            a0.x += v0*wv.x; a0.y += v0*wv.y; a0.z += v0*wv.z; a0.w += v0*wv.w;
            a1.x += v1*wv.x; a1.y += v1*wv.y; a1.z += v1*wv.z; a1.w += v1*wv.w;
            a2.x += v2*wv.x; a2.y += v2*wv.y; a2.z += v2*wv.z; a2.w += v2*wv.w;
            a3.x += v3*wv.x; a3.y += v3*wv.y; a3.z += v3*wv.z; a3.w += v3*wv.w;
        }
        #pragma unroll
        for (int kk = 0; kk < 16; kk++) {
            float4 wv = w1[kk];
            int k = kq * 32 + 16 + kk;
            float v0 = h_s[k], v1 = h_s[256 + k], v2 = h_s[512 + k], v3 = h_s[768 + k];
            a0.x += v0*wv.x; a0.y += v0*wv.y; a0.z += v0*wv.z; a0.w += v0*wv.w;
            a1.x += v1*wv.x; a1.y += v1*wv.y; a1.z += v1*wv.z; a1.w += v1*wv.w;
            a2.x += v2*wv.x; a2.y += v2*wv.y; a2.z += v2*wv.z; a2.w += v2*wv.w;
            a3.x += v3*wv.x; a3.y += v3*wv.y; a3.z += v3*wv.z; a3.w += v3*wv.w;
        }
        *(float4*)&s_red[(kq * 4 + 0) * 128 + cg * 4] = a0;
        *(float4*)&s_red[(kq * 4 + 1) * 128 + cg * 4] = a1;
        *(float4*)&s_red[(kq * 4 + 2) * 128 + cg * 4] = a2;
        *(float4*)&s_red[(kq * 4 + 3) * 128 + cg * 4] = a3;
        __syncthreads();

        float* ob = z ? (out + Bsz * Vv) : out;
        #pragma unroll
        for (int u = 0; u < 2; u++) {
            int idx = tid + u * 256;
            int r = idx >> 7, c = idx & 127;
            float s = 0.f;
            #pragma unroll
            for (int k2 = 0; k2 < 8; k2++) s += s_red[(k2 * 4 + r) * 128 + c];
            ob[(rowt * 4 + r) * OW + colt * 128 + c] = s + B2[colt * 128 + c];
        }
    }
}

// ---------------------------------------------------------------------------
extern "C" void kernel_launch(void* const* d_in, const int* in_sizes, int n_in,
                              void* d_out, int out_size)
{
    const int*   marker     = (const int*)d_in[0];
    const int*   srcI       = (const int*)d_in[1];
    const int*   sv         = (const int*)d_in[2];
    const int*   tsymI      = (const int*)d_in[3];
    const int*   tsv        = (const int*)d_in[4];
    const int*   tvalI      = (const int*)d_in[5];
    const int*   tvv        = (const int*)d_in[6];
    const int*   qI         = (const int*)d_in[7];
    const int*   qV         = (const int*)d_in[8];
    const float* evidence   = (const float*)d_in[9];
    const float* symbol_emb = (const float*)d_in[10];
    const float* value_emb  = (const float*)d_in[11];
    const float* Wmg1 = (const float*)d_in[12]; const float* bmg1 = (const float*)d_in[13];
    const float* Wmg2 = (const float*)d_in[14]; const float* bmg2 = (const float*)d_in[15];
    const float* Wsg1 = (const float*)d_in[16]; const float* bsg1 = (const float*)d_in[17];
    const float* Wsg2 = (const float*)d_in[18]; const float* bsg2 = (const float*)d_in[19];
    const float* Wf1  = (const float*)d_in[20]; const float* bf1  = (const float*)d_in[21];
    const float* Wf2  = (const float*)d_in[22]; const float* bf2  = (const float*)d_in[23];
    const float* Wo1  = (const float*)d_in[24]; const float* bo1  = (const float*)d_in[25];
    const float* Wo2  = (const float*)d_in[26]; const float* bo2  = (const float*)d_in[27];
    float* out = (float*)d_out;

    k_all<<<NB, 256>>>(marker, srcI, sv, tsymI, tsv, tvalI, tvv, qI, qV,
                       evidence, symbol_emb, value_emb,
                       Wmg1, bmg1, Wmg2, bmg2, Wsg1, bsg1, Wsg2, bsg2,
                       Wf1, bf1, Wf2, bf2, Wo1, bo1, Wo2, bo2, out);
}